// round 5
// baseline (speedup 1.0000x reference)
#include <cuda_runtime.h>
#include <cuda_fp16.h>
#include <cstdint>

// ---------------- problem constants ----------------
#define BATCH  16384
#define NFEAT  16
#define MTOT   4844
#define KPAD   4928          // 4844 + 84 run-pads = 77 * 64
#define KSTAGE 64
#define NSTAGE 77
#define OUTD   256
#define BM     128
#define NTHR   512
#define ROWB   144           // A/B smem row pitch (64 halves + 16B pad)
#define EDSTRIDE 155         // E_dup row stride in b32 words (odd -> conflict-free)

// SMEM layout (bytes)
#define A_BUFSZ 18432                          // 128 x 144
#define B_BUFSZ 36864                          // 256 x 144
#define A_OFF   0                              // 2 buffers
#define B_OFF   (2 * A_BUFSZ)                  // 36864, 2 buffers
#define ED_OFF  (B_OFF + 2 * B_BUFSZ)          // 110592: E_dup 128 x 155 x 4 = 79360
#define BIAS_OFF (ED_OFF + BM * EDSTRIDE * 4)  // 189952
#define SMEM_REQ (BIAS_OFF + OUTD * 4)         // 190976
// prologue scratch (overlaps A/B buffers, dead before pipeline starts):
#define TF_OFF  A_OFF                          // fp32 tanh: 128 x 17 x 4 = 8704
#define EH_OFF  B_OFF                          // fp16 E:    128 x 160 x 2 = 40960

// ---------------- device globals ----------------
__device__ __align__(16) __half   g_Wh[OUTD * KPAD];  // fp16 W, permuted K order
__device__ __align__(16) uint32_t g_TBLP[KPAD / 2];   // per-PAIR: e1 | (e2<<16)
__device__ int g_KMAP[KPAD];                          // new k -> original m (-1 = pad)

__device__ __forceinline__ int pair_rank(int a, int b) {
    return a * 16 - (a * (a - 1)) / 2 + (b - a);
}

// ---- prep 1: build run-padded K ordering, pair table, KMAP ----
// Runs (constant e1, e2 consecutive): run 0 = deg1+deg2 (e1=0, len 152);
// runs 1..16 = deg3 (a); runs 17..152 = deg4 (a,b) by pair rank. Odd runs pad +1.
__global__ void prep_map() {
    int m = blockIdx.x * blockDim.x + threadIdx.x;
    if (m >= MTOT) return;
    int run, off, len;
    uint32_t e1, e2;
    if (m < 152) {
        run = 0; off = m; len = 152; e1 = 0; e2 = 1 + m;
    } else if (m < 968) {
        int r = m - 152, a = 0;
        while (true) { int k = 16 - a; int t2 = k * (k + 1) / 2; if (r < t2) break; r -= t2; a++; }
        int praa = a * 16 - a * (a - 1) / 2;
        run = 1 + a; off = r; len = 136 - praa;
        e1 = 1 + a; e2 = 17 + praa + r;
    } else {
        int r = m - 968, a = 0;
        while (true) { int k = 16 - a; int t3 = k * (k + 1) * (k + 2) / 6; if (r < t3) break; r -= t3; a++; }
        int b = a;
        while (true) { int k = 16 - b; int t2 = k * (k + 1) / 2; if (r < t2) break; r -= t2; b++; }
        int prab = pair_rank(a, b);
        int prbb = b * 16 - b * (b - 1) / 2;
        run = 17 + prab; off = r; len = 136 - prbb;
        e1 = 17 + prab; e2 = 17 + prbb + r;
    }
    // padded start of this run
    int start = 0;
    for (int rr = 0; rr < run; ++rr) {
        int L;
        if (rr == 0) L = 152;
        else if (rr < 17) { int a2 = rr - 1; L = 136 - (a2 * 16 - a2 * (a2 - 1) / 2); }
        else {
            int t = rr - 17, a2 = 0;
            while (t >= 16 - a2) { t -= 16 - a2; a2++; }
            int b2 = a2 + t;
            L = 136 - (b2 * 16 - b2 * (b2 - 1) / 2);
        }
        start += (L + 1) & ~1;
    }
    int k = start + off;
    g_KMAP[k] = m;
    if (!(k & 1)) g_TBLP[k >> 1] = e1 | (e2 << 16);   // pair partner shares e1, e2+1
    if (off == len - 1 && (len & 1)) g_KMAP[k + 1] = -1;  // single pad slot (odd k)
}

// ---- prep 2: permuted fp16 W ----
__global__ void prep_w(const float* __restrict__ W) {
    int idx = blockIdx.x * blockDim.x + threadIdx.x;
    if (idx >= OUTD * KPAD) return;
    int n = idx / KPAD, k = idx - n * KPAD;
    int m = g_KMAP[k];
    float w = (m >= 0) ? W[(size_t)n * MTOT + m] : 0.0f;
    g_Wh[idx] = __float2half_rn(w);
}

// ---------------- PTX helpers (sm_80-level) ----------------
__device__ __forceinline__ uint32_t smem_u32(const void* p) {
    uint32_t a;
    asm("{ .reg .u64 t; cvta.to.shared.u64 t, %1; cvt.u32.u64 %0, t; }" : "=r"(a) : "l"(p));
    return a;
}
__device__ __forceinline__ void cp_async16(uint32_t dst, const void* src) {
    asm volatile("cp.async.cg.shared.global [%0], [%1], 16;" :: "r"(dst), "l"(src) : "memory");
}
__device__ __forceinline__ void ldsm_x4(uint32_t (&r)[4], uint32_t addr) {
    asm volatile("ldmatrix.sync.aligned.m8n8.x4.shared.b16 {%0,%1,%2,%3}, [%4];"
                 : "=r"(r[0]), "=r"(r[1]), "=r"(r[2]), "=r"(r[3]) : "r"(addr));
}
__device__ __forceinline__ void mma16816(float (&c)[4], const uint32_t (&a)[4],
                                         uint32_t b0, uint32_t b1) {
    asm volatile(
        "mma.sync.aligned.m16n8k16.row.col.f32.f16.f16.f32 "
        "{%0,%1,%2,%3}, {%4,%5,%6,%7}, {%8,%9}, {%0,%1,%2,%3};"
        : "+f"(c[0]), "+f"(c[1]), "+f"(c[2]), "+f"(c[3])
        : "r"(a[0]), "r"(a[1]), "r"(a[2]), "r"(a[3]), "r"(b0), "r"(b1));
}

// ---------------- main fused kernel (R3 flow + pair-gen) ----------------
__global__ void __launch_bounds__(NTHR, 1) taylor_main(
    const float* __restrict__ x,
    const float* __restrict__ bias,
    float* __restrict__ out)
{
    extern __shared__ char smem[];
    const uint32_t sbase = smem_u32(smem);
    float* Bias = (float*)(smem + BIAS_OFF);

    const int tid  = threadIdx.x;
    const int wid  = tid >> 5;
    const int lane = tid & 31;
    const int b0   = blockIdx.x * BM;
    const int wm   = wid & 3;
    const int wn   = wid >> 2;

    // ==== prologue: build fp16 pair-packed E table ====
    {
        float* Tf = (float*)(smem + TF_OFF);          // [128][17] fp32 tanh
        __half* Eh = (__half*)(smem + EH_OFF);        // [128][160] fp16 E entries
        #pragma unroll
        for (int i = 0; i < (BM * NFEAT) / NTHR; ++i) {
            int q = tid + i * NTHR;
            int row = q >> 4, f = q & 15;
            float t = tanhf(x[(size_t)(b0 + row) * NFEAT + f]);
            Tf[row * 17 + f] = t;
            Eh[row * 160 + 1 + f] = __float2half_rn(t);
        }
        if (tid < BM) {
            Eh[tid * 160 + 0]   = __float2half_rn(1.0f);
            Eh[tid * 160 + 153] = __ushort_as_half(0);
            Eh[tid * 160 + 154] = __ushort_as_half(0);
        }
        if (tid < OUTD) Bias[tid] = bias[tid];
        __syncthreads();
        // pairwise products (fp32 math, single rounding)
        #pragma unroll
        for (int i = 0; i < (136 * BM) / NTHR; ++i) {
            int q = tid + i * NTHR;
            int row = q & 127, p = q >> 7;
            // unrank pair p -> (a,b)
            int r = p, a = 0;
            while (r >= 16 - a) { r -= 16 - a; a++; }
            int b = a + r;
            Eh[row * 160 + 17 + p] = __float2half_rn(Tf[row * 17 + a] * Tf[row * 17 + b]);
        }
        __syncthreads();
        // pack adjacent pairs: E_dup[row][i] = (Eh[i], Eh[i+1])
        uint32_t* Ed = (uint32_t*)(smem + ED_OFF);
        const int row = tid & 127;
        const __half* ehr = Eh + row * 160;
        for (int c = tid >> 7; c < 154; c += 4) {
            uint32_t lo = __half_as_ushort(ehr[c]);
            uint32_t hi = __half_as_ushort(ehr[c + 1]);
            Ed[row * EDSTRIDE + c] = lo | (hi << 16);
        }
        __syncthreads();   // E_dup complete; Tf/Eh scratch now dead
    }

    // ==== per-thread gen assignment ====
    const int grow = tid & 127;
    const int gkb  = (tid >> 7) << 4;                 // k offset within stage: 0/16/32/48
    const uint32_t eRow = sbase + ED_OFF + grow * (EDSTRIDE * 4);
    const uint32_t gAaddr = sbase + A_OFF + grow * ROWB + gkb * 2;

    // gen 16 monomials (8 pairs) + store to A buffer
    #define GEN_A(s_, buf_) do {                                                    \
        const int pb = (s_) * 32 + (gkb >> 1);                                      \
        uint32_t t0_[4], t1_[4];                                                    \
        *(uint4*)t0_ = *(const uint4*)&g_TBLP[pb];                                  \
        *(uint4*)t1_ = *(const uint4*)&g_TBLP[pb + 4];                              \
        uint32_t hh[8];                                                             \
        _Pragma("unroll")                                                           \
        for (int q = 0; q < 8; ++q) {                                               \
            uint32_t t = (q < 4) ? t0_[q] : t1_[q - 4];                             \
            uint32_t pv, ev, eb;                                                    \
            asm("ld.shared.b32 %0, [%1];" : "=r"(pv) : "r"(eRow + ((t >> 16) << 2)));\
            asm("ld.shared.b32 %0, [%1];" : "=r"(ev) : "r"(eRow + ((t & 0xffffu) << 2)));\
            asm("prmt.b32 %0, %1, %1, 0x1010;" : "=r"(eb) : "r"(ev));               \
            asm("mul.rn.f16x2 %0, %1, %2;" : "=r"(hh[q]) : "r"(pv), "r"(eb));       \
        }                                                                           \
        uint32_t ad = gAaddr + (buf_) * A_BUFSZ;                                    \
        asm volatile("st.shared.v4.b32 [%0], {%1,%2,%3,%4};"                        \
                     :: "r"(ad), "r"(hh[0]), "r"(hh[1]), "r"(hh[2]), "r"(hh[3]) : "memory"); \
        asm volatile("st.shared.v4.b32 [%0], {%1,%2,%3,%4};"                        \
                     :: "r"(ad + 16), "r"(hh[4]), "r"(hh[5]), "r"(hh[6]), "r"(hh[7]) : "memory"); \
    } while (0)

    #define LOAD_B(s_, buf_) do {                                                   \
        _Pragma("unroll")                                                           \
        for (int i = 0; i < 4; ++i) {                                               \
            int c = tid + i * NTHR;                                                 \
            int row = c >> 3, seg = c & 7;                                          \
            const __half* src = g_Wh + (size_t)row * KPAD + (s_) * KSTAGE + seg * 8;\
            cp_async16(sbase + B_OFF + (buf_) * B_BUFSZ + row * ROWB + seg * 16, src);\
        }                                                                           \
        asm volatile("cp.async.commit_group;" ::: "memory");                        \
    } while (0)

    // ---- pipeline prologue ----
    GEN_A(0, 0); LOAD_B(0, 0);
    GEN_A(1, 1); LOAD_B(1, 1);

    float acc[2][8][4];
    #pragma unroll
    for (int i = 0; i < 2; ++i)
        #pragma unroll
        for (int j = 0; j < 8; ++j)
            #pragma unroll
            for (int q = 0; q < 4; ++q) acc[i][j][q] = 0.0f;

    const uint32_t aRowAddr = sbase + A_OFF + (wm * 32 + (lane & 15)) * ROWB + (lane >> 4) * 16;
    const int bq = lane >> 3;
    const uint32_t bRowAddr = sbase + B_OFF + (wn * 64 + ((bq >> 1) << 3) + (lane & 7)) * ROWB + (bq & 1) * 16;

    // ---- main loop (R3 flow: compute, then gen/load 2-ahead) ----
    for (int s = 0; s < NSTAGE; ++s) {
        const int buf = s & 1;
        if (s == NSTAGE - 1)
            asm volatile("cp.async.wait_group 0;" ::: "memory");
        else
            asm volatile("cp.async.wait_group 1;" ::: "memory");
        __syncthreads();   // B(s) + A(s) visible

        const uint32_t aB = aRowAddr + buf * A_BUFSZ;
        const uint32_t bB = bRowAddr + buf * B_BUFSZ;
        #pragma unroll
        for (int kf = 0; kf < 4; ++kf) {
            uint32_t a[2][4];
            ldsm_x4(a[0], aB + kf * 32);
            ldsm_x4(a[1], aB + kf * 32 + 16 * ROWB);
            #pragma unroll
            for (int nb = 0; nb < 4; ++nb) {
                uint32_t b[4];
                ldsm_x4(b, bB + nb * 16 * ROWB + kf * 32);
                mma16816(acc[0][nb * 2 + 0], a[0], b[0], b[1]);
                mma16816(acc[0][nb * 2 + 1], a[0], b[2], b[3]);
                mma16816(acc[1][nb * 2 + 0], a[1], b[0], b[1]);
                mma16816(acc[1][nb * 2 + 1], a[1], b[2], b[3]);
            }
        }
        __syncthreads();   // all warps done reading buf

        if (s + 2 < NSTAGE) {
            GEN_A(s + 2, buf);
            LOAD_B(s + 2, buf);
        }
    }

    // ---- epilogue: bias + relu + store ----
    {
        const int rbase = b0 + wm * 32 + (lane >> 2);
        const int cbase = wn * 64 + (lane & 3) * 2;
        #pragma unroll
        for (int mf = 0; mf < 2; ++mf) {
            #pragma unroll
            for (int nf = 0; nf < 8; ++nf) {
                const int col = cbase + nf * 8;
                const float bz0 = Bias[col], bz1 = Bias[col + 1];
                const int r0 = rbase + mf * 16;
                float2 v0, v1;
                v0.x = fmaxf(acc[mf][nf][0] + bz0, 0.0f);
                v0.y = fmaxf(acc[mf][nf][1] + bz1, 0.0f);
                v1.x = fmaxf(acc[mf][nf][2] + bz0, 0.0f);
                v1.y = fmaxf(acc[mf][nf][3] + bz1, 0.0f);
                *reinterpret_cast<float2*>(out + (size_t)r0 * OUTD + col)       = v0;
                *reinterpret_cast<float2*>(out + (size_t)(r0 + 8) * OUTD + col) = v1;
            }
        }
    }
    #undef GEN_A
    #undef LOAD_B
}

// ---------------- launch ----------------
extern "C" void kernel_launch(void* const* d_in, const int* in_sizes, int n_in,
                              void* d_out, int out_size) {
    const float* x = (const float*)d_in[0];
    const float* W = (const float*)d_in[1];
    const float* b = (const float*)d_in[2];
    float* out = (float*)d_out;

    cudaFuncSetAttribute(taylor_main, cudaFuncAttributeMaxDynamicSharedMemorySize, SMEM_REQ);

    prep_map<<<(MTOT + 255) / 256, 256>>>();
    prep_w<<<(OUTD * KPAD + 255) / 256, 256>>>(W);
    taylor_main<<<BATCH / BM, NTHR, SMEM_REQ>>>(x, b, out);
}

// round 7
// speedup vs baseline: 1.1450x; 1.1450x over previous
#include <cuda_runtime.h>
#include <cuda_fp16.h>
#include <cstdint>

// ---------------- problem constants ----------------
#define BATCH  16384
#define NFEAT  16
#define MTOT   4844
#define KPAD   4864          // padded K (mult of 64); pad monomial = 1, pad W = 0
#define KSTAGE 64
#define NSTAGE 76
#define OUTD   256
#define BM     128
#define NTHR   1024          // 32 warps: 4 (M) x 8 (N)
#define ESTRIDE 155          // E-table row stride in floats (odd -> conflict-free)
#define ROWB   144           // A/B smem row pitch (64 halves + 16B pad)

// SMEM layout (bytes)
#define A_BUFSZ 18432                          // 128 x 144
#define B_BUFSZ 36864                          // 256 x 144
#define A_OFF   0                              // 2 buffers
#define B_OFF   (2 * A_BUFSZ)                  // 36864, 2 buffers
#define E_OFF   (B_OFF + 2 * B_BUFSZ)          // 110592: E 128 x 155 x 4 = 79360
#define BIAS_OFF (E_OFF + BM * ESTRIDE * 4)    // 189952
#define SMEM_REQ (BIAS_OFF + OUTD * 4)         // 190976

// ---------------- device globals ----------------
__device__ __align__(16) __half   g_Wh[OUTD * KPAD];  // fp16 W [N=256][KPAD]
__device__ __align__(16) uint32_t g_TBL[KPAD];        // monomial m -> e1 | (e2<<16)
__device__ uint32_t g_PAIRT[136];                     // pair rank -> a | (b<<8)

__device__ __forceinline__ int pair_rank(int a, int b) {
    return a * 16 - (a * (a - 1)) / 2 + (b - a);
}

// Merged prep (one launch): pair table + monomial unranking (validated R1) + fp16 W.
__global__ void prep_all(const float* __restrict__ W) {
    int idx = blockIdx.x * blockDim.x + threadIdx.x;
    if (idx < 136) {
        int r = idx, a = 0;
        while (r >= 16 - a) { r -= 16 - a; a++; }
        g_PAIRT[idx] = (uint32_t)a | ((uint32_t)(a + r) << 8);
    }
    if (idx < KPAD) {
        int m = idx;
        uint32_t e1 = 0, e2 = 0;
        if (m < 16) {
            e1 = 1 + m; e2 = 0;
        } else if (m < 152) {
            e1 = 17 + (m - 16); e2 = 0;
        } else if (m < 968) {
            int r = m - 152, a = 0;
            while (true) { int k = 16 - a; int t2 = k * (k + 1) / 2; if (r < t2) break; r -= t2; a++; }
            int b = a;
            while (r >= 16 - b) { r -= 16 - b; b++; }
            int c = b + r;
            e1 = 1 + a; e2 = 17 + pair_rank(b, c);
        } else if (m < MTOT) {
            int r = m - 968, a = 0;
            while (true) { int k = 16 - a; int t3 = k * (k + 1) * (k + 2) / 6; if (r < t3) break; r -= t3; a++; }
            int b = a;
            while (true) { int k = 16 - b; int t2 = k * (k + 1) / 2; if (r < t2) break; r -= t2; b++; }
            int c = b;
            while (r >= 16 - c) { r -= 16 - c; c++; }
            int d = c + r;
            e1 = 17 + pair_rank(a, b); e2 = 17 + pair_rank(c, d);
        } else {
            e1 = 0; e2 = 0;   // pad: monomial 1*1, weight forced to 0
        }
        g_TBL[m] = e1 | (e2 << 16);
    }
    if (idx < OUTD * KPAD) {
        int n = idx / KPAD, k = idx - n * KPAD;
        float w = (k < MTOT) ? W[(size_t)n * MTOT + k] : 0.0f;
        g_Wh[idx] = __float2half_rn(w);
    }
}

// ---------------- PTX helpers (sm_80-level) ----------------
__device__ __forceinline__ uint32_t smem_u32(const void* p) {
    uint32_t a;
    asm("{ .reg .u64 t; cvta.to.shared.u64 t, %1; cvt.u32.u64 %0, t; }" : "=r"(a) : "l"(p));
    return a;
}
__device__ __forceinline__ void cp_async16(uint32_t dst, const void* src) {
    asm volatile("cp.async.cg.shared.global [%0], [%1], 16;" :: "r"(dst), "l"(src) : "memory");
}
__device__ __forceinline__ void ldsm_x4(uint32_t (&r)[4], uint32_t addr) {
    asm volatile("ldmatrix.sync.aligned.m8n8.x4.shared.b16 {%0,%1,%2,%3}, [%4];"
                 : "=r"(r[0]), "=r"(r[1]), "=r"(r[2]), "=r"(r[3]) : "r"(addr));
}
__device__ __forceinline__ void mma16816(float (&c)[4], const uint32_t (&a)[4],
                                         uint32_t b0, uint32_t b1) {
    asm volatile(
        "mma.sync.aligned.m16n8k16.row.col.f32.f16.f16.f32 "
        "{%0,%1,%2,%3}, {%4,%5,%6,%7}, {%8,%9}, {%0,%1,%2,%3};"
        : "+f"(c[0]), "+f"(c[1]), "+f"(c[2]), "+f"(c[3])
        : "r"(a[0]), "r"(a[1]), "r"(a[2]), "r"(a[3]), "r"(b0), "r"(b1));
}

// ---------------- main fused kernel ----------------
// 128 CTAs x 1024 threads; CTA tile M=128 x N=256, K staged by 64.
// 32 warps 4x8: warp (wm,wn) owns rows wm*32..+32, cols wn*32..+32.
__global__ void __launch_bounds__(NTHR, 1) taylor_main(
    const float* __restrict__ x,
    const float* __restrict__ bias,
    float* __restrict__ out)
{
    extern __shared__ char smem[];
    const uint32_t sbase = smem_u32(smem);
    float* E    = (float*)(smem + E_OFF);
    float* Bias = (float*)(smem + BIAS_OFF);

    const int tid  = threadIdx.x;
    const int wid  = tid >> 5;
    const int lane = tid & 31;
    const int b0   = blockIdx.x * BM;
    const int wm   = wid & 3;    // M block (32 rows)
    const int wn   = wid >> 2;   // N block (32 cols)

    // ---- prologue: tanh + pairwise products into E (fp32) ----
    #pragma unroll
    for (int i = 0; i < (BM * NFEAT) / NTHR; ++i) {
        int q = tid + i * NTHR;
        int row = q >> 4, f = q & 15;
        E[row * ESTRIDE + 1 + f] = tanhf(x[(size_t)(b0 + row) * NFEAT + f]);
    }
    if (tid < BM)   E[tid * ESTRIDE] = 1.0f;
    if (tid < OUTD) Bias[tid] = bias[tid];
    __syncthreads();
    #pragma unroll
    for (int i = 0; i < (136 * BM) / NTHR; ++i) {
        int q = tid + i * NTHR;
        int row = q & 127, p = q >> 7;
        uint32_t pr = g_PAIRT[p];
        E[row * ESTRIDE + 17 + p] =
            E[row * ESTRIDE + 1 + (pr & 255)] * E[row * ESTRIDE + 1 + ((pr >> 8) & 255)];
    }
    __syncthreads();

    // per-thread gen assignment: row = tid & 127, k-block of 8 = tid >> 7
    const int grow = tid & 127;
    const int gkb  = (tid >> 7) << 3;     // 0..56 step 8
    const float* Er = E + grow * ESTRIDE;
    const uint32_t gAaddr = sbase + A_OFF + grow * ROWB + gkb * 2;

    // gen 8 monomials + store (one 16B STS)
    #define GEN_A(s_, buf_) do {                                                    \
        const int mb = (s_) * KSTAGE + gkb;                                         \
        uint32_t tt[8];                                                             \
        *(uint4*)&tt[0] = *(const uint4*)&g_TBL[mb];                                \
        *(uint4*)&tt[4] = *(const uint4*)&g_TBL[mb + 4];                            \
        uint32_t hh[4];                                                             \
        _Pragma("unroll")                                                           \
        for (int q = 0; q < 4; ++q) {                                               \
            uint32_t t0 = tt[2 * q], t1 = tt[2 * q + 1];                            \
            float v0 = Er[t0 & 0xffff] * Er[t0 >> 16];                              \
            float v1 = Er[t1 & 0xffff] * Er[t1 >> 16];                              \
            asm("cvt.rn.f16x2.f32 %0, %1, %2;" : "=r"(hh[q]) : "f"(v1), "f"(v0));   \
        }                                                                           \
        asm volatile("st.shared.v4.b32 [%0], {%1,%2,%3,%4};"                        \
                     :: "r"(gAaddr + (buf_) * A_BUFSZ),                             \
                        "r"(hh[0]), "r"(hh[1]), "r"(hh[2]), "r"(hh[3]) : "memory"); \
    } while (0)

    // B stage: 256 rows x 8 chunks of 16B = 2048 chunks = 2 per thread (EXACT)
    #define LOAD_B(s_, buf_) do {                                                   \
        _Pragma("unroll")                                                           \
        for (int i = 0; i < 2; ++i) {                                               \
            int c = tid + i * NTHR;                                                 \
            int row = c >> 3, seg = c & 7;                                          \
            const __half* src = g_Wh + (size_t)row * KPAD + (s_) * KSTAGE + seg * 8;\
            cp_async16(sbase + B_OFF + (buf_) * B_BUFSZ + row * ROWB + seg * 16, src);\
        }                                                                           \
        asm volatile("cp.async.commit_group;" ::: "memory");                        \
    } while (0)

    // ---- pipeline prologue ----
    GEN_A(0, 0); LOAD_B(0, 0);
    GEN_A(1, 1); LOAD_B(1, 1);

    float acc[2][4][4];   // [m-half 16][n8 group][frag]
    #pragma unroll
    for (int i = 0; i < 2; ++i)
        #pragma unroll
        for (int j = 0; j < 4; ++j)
            #pragma unroll
            for (int q = 0; q < 4; ++q) acc[i][j][q] = 0.0f;

    const uint32_t aRowAddr = sbase + A_OFF + (wm * 32 + (lane & 15)) * ROWB + (lane >> 4) * 16;
    const int bq = lane >> 3;
    const uint32_t bRowAddr = sbase + B_OFF + (wn * 32 + ((bq >> 1) << 3) + (lane & 7)) * ROWB + (bq & 1) * 16;

    // ---- main loop ----
    for (int s = 0; s < NSTAGE; ++s) {
        const int buf = s & 1;
        if (s == NSTAGE - 1)
            asm volatile("cp.async.wait_group 0;" ::: "memory");
        else
            asm volatile("cp.async.wait_group 1;" ::: "memory");
        __syncthreads();   // B(s) + A(s) visible

        const uint32_t aB = aRowAddr + buf * A_BUFSZ;
        const uint32_t bB = bRowAddr + buf * B_BUFSZ;
        #pragma unroll
        for (int kf = 0; kf < 4; ++kf) {
            uint32_t a[2][4];
            ldsm_x4(a[0], aB + kf * 32);
            ldsm_x4(a[1], aB + kf * 32 + 16 * ROWB);
            #pragma unroll
            for (int nb = 0; nb < 2; ++nb) {
                uint32_t b[4];
                ldsm_x4(b, bB + nb * 16 * ROWB + kf * 32);
                mma16816(acc[0][nb * 2 + 0], a[0], b[0], b[1]);
                mma16816(acc[0][nb * 2 + 1], a[0], b[2], b[3]);
                mma16816(acc[1][nb * 2 + 0], a[1], b[0], b[1]);
                mma16816(acc[1][nb * 2 + 1], a[1], b[2], b[3]);
            }
        }
        __syncthreads();   // all warps done reading buf

        if (s + 2 < NSTAGE) {
            GEN_A(s + 2, buf);
            LOAD_B(s + 2, buf);
        }
    }

    // ---- epilogue: bias + relu + store ----
    {
        const int rbase = b0 + wm * 32 + (lane >> 2);
        const int cbase = wn * 32 + (lane & 3) * 2;
        #pragma unroll
        for (int mf = 0; mf < 2; ++mf) {
            #pragma unroll
            for (int nf = 0; nf < 4; ++nf) {
                const int col = cbase + nf * 8;
                const float bz0 = Bias[col], bz1 = Bias[col + 1];
                const int r0 = rbase + mf * 16;
                float2 v0, v1;
                v0.x = fmaxf(acc[mf][nf][0] + bz0, 0.0f);
                v0.y = fmaxf(acc[mf][nf][1] + bz1, 0.0f);
                v1.x = fmaxf(acc[mf][nf][2] + bz0, 0.0f);
                v1.y = fmaxf(acc[mf][nf][3] + bz1, 0.0f);
                *reinterpret_cast<float2*>(out + (size_t)r0 * OUTD + col)       = v0;
                *reinterpret_cast<float2*>(out + (size_t)(r0 + 8) * OUTD + col) = v1;
            }
        }
    }
    #undef GEN_A
    #undef LOAD_B
}

// ---------------- launch ----------------
extern "C" void kernel_launch(void* const* d_in, const int* in_sizes, int n_in,
                              void* d_out, int out_size) {
    const float* x = (const float*)d_in[0];
    const float* W = (const float*)d_in[1];
    const float* b = (const float*)d_in[2];
    float* out = (float*)d_out;

    cudaFuncSetAttribute(taylor_main, cudaFuncAttributeMaxDynamicSharedMemorySize, SMEM_REQ);

    prep_all<<<(OUTD * KPAD + 255) / 256, 256>>>(W);
    taylor_main<<<BATCH / BM, NTHR, SMEM_REQ>>>(x, b, out);
}

// round 8
// speedup vs baseline: 1.2623x; 1.1024x over previous
#include <cuda_runtime.h>
#include <cuda_fp16.h>
#include <cstdint>

// ---------------- problem constants ----------------
#define BATCH  16384
#define NFEAT  16
#define MTOT   4844
#define KPAD   4864          // pad monomial = 1, pad W = 0
#define KSTAGE 64
#define NSTAGE 76
#define OUTD   256
#define BM     128
#define NTHR   512           // 16 warps: 4 (M32) x 4 (N64)
#define ESTRIDE 155          // E row stride in floats (odd -> conflict-free)

// SMEM layout: XOR-swizzled rows, 128B pitch, no pad
#define A_BUFSZ 16384                          // 128 x 128B
#define B_BUFSZ 32768                          // 256 x 128B
#define A_OFF   0                              // 3 buffers -> 49152
#define B_OFF   (3 * A_BUFSZ)                  // 49152, 3 buffers -> +98304
#define E_OFF   (B_OFF + 3 * B_BUFSZ)          // 147456, E: 128*155*4 = 79360
#define BIAS_OFF (E_OFF + BM * ESTRIDE * 4)    // 226816
#define SMEM_REQ (BIAS_OFF + OUTD * 4)         // 227840  (< 232448 cap)

// ---------------- device globals ----------------
__device__ __align__(16) __half   g_Wh[OUTD * KPAD];  // fp16 W [N=256][KPAD]
__device__ __align__(16) uint32_t g_TBL[KPAD];        // m -> e1 | (e2<<16)
__device__ uint32_t g_PAIRT[136];

__device__ __forceinline__ int pair_rank(int a, int b) {
    return a * 16 - (a * (a - 1)) / 2 + (b - a);
}

__global__ void prep_all(const float* __restrict__ W) {
    int idx = blockIdx.x * blockDim.x + threadIdx.x;
    if (idx < 136) {
        int r = idx, a = 0;
        while (r >= 16 - a) { r -= 16 - a; a++; }
        g_PAIRT[idx] = (uint32_t)a | ((uint32_t)(a + r) << 8);
    }
    if (idx < KPAD) {
        int m = idx;
        uint32_t e1 = 0, e2 = 0;
        if (m < 16) {
            e1 = 1 + m; e2 = 0;
        } else if (m < 152) {
            e1 = 17 + (m - 16); e2 = 0;
        } else if (m < 968) {
            int r = m - 152, a = 0;
            while (true) { int k = 16 - a; int t2 = k * (k + 1) / 2; if (r < t2) break; r -= t2; a++; }
            int b = a;
            while (r >= 16 - b) { r -= 16 - b; b++; }
            int c = b + r;
            e1 = 1 + a; e2 = 17 + pair_rank(b, c);
        } else if (m < MTOT) {
            int r = m - 968, a = 0;
            while (true) { int k = 16 - a; int t3 = k * (k + 1) * (k + 2) / 6; if (r < t3) break; r -= t3; a++; }
            int b = a;
            while (true) { int k = 16 - b; int t2 = k * (k + 1) / 2; if (r < t2) break; r -= t2; b++; }
            int c = b;
            while (r >= 16 - c) { r -= 16 - c; c++; }
            int d = c + r;
            e1 = 17 + pair_rank(a, b); e2 = 17 + pair_rank(c, d);
        } else {
            e1 = 0; e2 = 0;
        }
        g_TBL[m] = e1 | (e2 << 16);
    }
    if (idx < OUTD * KPAD) {
        int n = idx / KPAD, k = idx - n * KPAD;
        float w = (k < MTOT) ? W[(size_t)n * MTOT + k] : 0.0f;
        g_Wh[idx] = __float2half_rn(w);
    }
}

// ---------------- PTX helpers ----------------
__device__ __forceinline__ uint32_t smem_u32(const void* p) {
    uint32_t a;
    asm("{ .reg .u64 t; cvta.to.shared.u64 t, %1; cvt.u32.u64 %0, t; }" : "=r"(a) : "l"(p));
    return a;
}
__device__ __forceinline__ void cp_async16(uint32_t dst, const void* src) {
    asm volatile("cp.async.cg.shared.global [%0], [%1], 16;" :: "r"(dst), "l"(src) : "memory");
}
__device__ __forceinline__ void ldsm_x4(uint32_t (&r)[4], uint32_t addr) {
    asm volatile("ldmatrix.sync.aligned.m8n8.x4.shared.b16 {%0,%1,%2,%3}, [%4];"
                 : "=r"(r[0]), "=r"(r[1]), "=r"(r[2]), "=r"(r[3]) : "r"(addr));
}
__device__ __forceinline__ void mma16816(float (&c)[4], const uint32_t (&a)[4],
                                         uint32_t b0, uint32_t b1) {
    asm volatile(
        "mma.sync.aligned.m16n8k16.row.col.f32.f16.f16.f32 "
        "{%0,%1,%2,%3}, {%4,%5,%6,%7}, {%8,%9}, {%0,%1,%2,%3};"
        : "+f"(c[0]), "+f"(c[1]), "+f"(c[2]), "+f"(c[3])
        : "r"(a[0]), "r"(a[1]), "r"(a[2]), "r"(a[3]), "r"(b0), "r"(b1));
}

// ---------------- main fused kernel ----------------
// 128 CTAs x 512 threads; CTA tile M=128 x N=256; 16 warps (wm 0..3, wn 0..3)
// warp tile M32 x N64. 3-deep A and B buffers; ONE __syncthreads per stage.
// Rows are 128B with 16B-chunk XOR swizzle: phys_seg = log_seg ^ (row & 7).
__global__ void __launch_bounds__(NTHR, 1) taylor_main(
    const float* __restrict__ x,
    const float* __restrict__ bias,
    float* __restrict__ out)
{
    extern __shared__ char smem[];
    const uint32_t sbase = smem_u32(smem);
    float* E    = (float*)(smem + E_OFF);
    float* Bias = (float*)(smem + BIAS_OFF);

    const int tid  = threadIdx.x;
    const int wid  = tid >> 5;
    const int lane = tid & 31;
    const int b0   = blockIdx.x * BM;
    const int wm   = wid & 3;    // M block (32 rows)
    const int wn   = wid >> 2;   // N block (64 cols)

    // ---- prologue: tanh + pairwise products into E (fp32, exact R3 numerics) ----
    #pragma unroll
    for (int i = 0; i < (BM * NFEAT) / NTHR; ++i) {
        int q = tid + i * NTHR;
        int row = q >> 4, f = q & 15;
        E[row * ESTRIDE + 1 + f] = tanhf(x[(size_t)(b0 + row) * NFEAT + f]);
    }
    if (tid < BM)   E[tid * ESTRIDE] = 1.0f;
    if (tid < OUTD) Bias[tid] = bias[tid];
    __syncthreads();
    #pragma unroll
    for (int i = 0; i < (136 * BM) / NTHR; ++i) {
        int q = tid + i * NTHR;
        int row = q & 127, p = q >> 7;
        uint32_t pr = g_PAIRT[p];
        E[row * ESTRIDE + 17 + p] =
            E[row * ESTRIDE + 1 + (pr & 255)] * E[row * ESTRIDE + 1 + ((pr >> 8) & 255)];
    }
    __syncthreads();

    // ---- gen assignment: row = tid&127, 16 k per thread at gkb ----
    const int grow = tid & 127;
    const int gkb  = (tid >> 7) << 4;      // 0,16,32,48
    const int gseg = gkb >> 3;             // logical 16B seg: 0,2,4,6
    const int grb  = grow & 7;
    const float* Er = E + grow * ESTRIDE;
    const uint32_t gA0 = sbase + A_OFF + grow * 128 + (uint32_t)((gseg    ) ^ grb) * 16;
    const uint32_t gA1 = sbase + A_OFF + grow * 128 + (uint32_t)((gseg + 1) ^ grb) * 16;

    #define GEN_A(s_, bo_) do {                                                     \
        const int mb = (s_) * KSTAGE + gkb;                                         \
        uint32_t tt[16];                                                            \
        *(uint4*)&tt[0]  = *(const uint4*)&g_TBL[mb];                               \
        *(uint4*)&tt[4]  = *(const uint4*)&g_TBL[mb + 4];                           \
        *(uint4*)&tt[8]  = *(const uint4*)&g_TBL[mb + 8];                           \
        *(uint4*)&tt[12] = *(const uint4*)&g_TBL[mb + 12];                          \
        uint32_t hh[8];                                                             \
        _Pragma("unroll")                                                           \
        for (int q = 0; q < 8; ++q) {                                               \
            uint32_t t0 = tt[2 * q], t1 = tt[2 * q + 1];                            \
            float v0 = Er[t0 & 0xffff] * Er[t0 >> 16];                              \
            float v1 = Er[t1 & 0xffff] * Er[t1 >> 16];                              \
            asm("cvt.rn.f16x2.f32 %0, %1, %2;" : "=r"(hh[q]) : "f"(v1), "f"(v0));   \
        }                                                                           \
        asm volatile("st.shared.v4.b32 [%0], {%1,%2,%3,%4};"                        \
                     :: "r"(gA0 + (bo_)), "r"(hh[0]), "r"(hh[1]), "r"(hh[2]), "r"(hh[3]) : "memory"); \
        asm volatile("st.shared.v4.b32 [%0], {%1,%2,%3,%4};"                        \
                     :: "r"(gA1 + (bo_)), "r"(hh[4]), "r"(hh[5]), "r"(hh[6]), "r"(hh[7]) : "memory"); \
    } while (0)

    // B stage: 256 rows x 8 segs = 2048 chunks = 4 per thread (EXACT at 512 thr)
    #define LOAD_B(s_, bo_) do {                                                    \
        _Pragma("unroll")                                                           \
        for (int i = 0; i < 4; ++i) {                                               \
            int c = tid + i * NTHR;                                                 \
            int row = c >> 3, seg = c & 7;                                          \
            const __half* src = g_Wh + (size_t)row * KPAD + (s_) * KSTAGE + seg * 8;\
            cp_async16(sbase + B_OFF + (bo_) + row * 128 +                          \
                       (uint32_t)(seg ^ (row & 7)) * 16, src);                      \
        }                                                                           \
        asm volatile("cp.async.commit_group;" ::: "memory");                        \
    } while (0)

    // ---- pipeline prologue: stages 0,1 into bufs 0,1 ----
    GEN_A(0, 0);
    LOAD_B(0, 0);
    GEN_A(1, B_BUFSZ * 0 + A_BUFSZ);   // A buf 1
    LOAD_B(1, B_BUFSZ);                // B buf 1

    float acc[2][8][4];
    #pragma unroll
    for (int i = 0; i < 2; ++i)
        #pragma unroll
        for (int j = 0; j < 8; ++j)
            #pragma unroll
            for (int q = 0; q < 4; ++q) acc[i][j][q] = 0.0f;

    // ldsm lane addressing (logical seg + row -> phys via xor)
    const int ra   = wm * 32 + (lane & 15);
    const int arb  = ra & 7;
    const int alog = lane >> 4;                       // 0 or 1
    const uint32_t aBase = sbase + A_OFF + ra * 128;  // + bufoff + seg*16

    const int bq    = lane >> 3;
    const int rbrow = wn * 64 + ((bq >> 1) << 3) + (lane & 7);
    const int brb   = rbrow & 7;
    const int blog  = bq & 1;
    const uint32_t bBase = sbase + B_OFF + rbrow * 128;

    int bufA = 0, bufB = 0;            // byte offsets of buf s%3
    int bufA2 = 2 * A_BUFSZ, bufB2 = 2 * B_BUFSZ;   // byte offsets of buf (s+2)%3

    for (int s = 0; s < NSTAGE; ++s) {
        if (s == NSTAGE - 1)
            asm volatile("cp.async.wait_group 0;" ::: "memory");
        else
            asm volatile("cp.async.wait_group 1;" ::: "memory");
        __syncthreads();   // single bar: B(s)/A(s) visible; s-1 buffers vacated

        if (s + 2 < NSTAGE) {
            LOAD_B(s + 2, bufB2);      // cps in flight during gen + mma
            GEN_A(s + 2, bufA2);
        }

        const uint32_t aB = aBase + bufA;
        const uint32_t bB = bBase + bufB;
        #pragma unroll
        for (int kf = 0; kf < 4; ++kf) {
            uint32_t a[2][4];
            const uint32_t aoff = (uint32_t)((alog + 2 * kf) ^ arb) * 16;
            ldsm_x4(a[0], aB + aoff);
            ldsm_x4(a[1], aB + aoff + 16 * 128);
            const uint32_t boff = (uint32_t)((blog + 2 * kf) ^ brb) * 16;
            #pragma unroll
            for (int nb = 0; nb < 4; ++nb) {
                uint32_t b[4];
                ldsm_x4(b, bB + nb * (16 * 128) + boff);
                mma16816(acc[0][nb * 2 + 0], a[0], b[0], b[1]);
                mma16816(acc[0][nb * 2 + 1], a[0], b[2], b[3]);
                mma16816(acc[1][nb * 2 + 0], a[1], b[0], b[1]);
                mma16816(acc[1][nb * 2 + 1], a[1], b[2], b[3]);
            }
        }

        // advance ring offsets
        bufA += A_BUFSZ;  if (bufA  == 3 * A_BUFSZ) bufA  = 0;
        bufB += B_BUFSZ;  if (bufB  == 3 * B_BUFSZ) bufB  = 0;
        bufA2 += A_BUFSZ; if (bufA2 == 3 * A_BUFSZ) bufA2 = 0;
        bufB2 += B_BUFSZ; if (bufB2 == 3 * B_BUFSZ) bufB2 = 0;
    }

    // ---- epilogue: bias + relu + store ----
    {
        const int rbase = b0 + wm * 32 + (lane >> 2);
        const int cbase = wn * 64 + (lane & 3) * 2;
        #pragma unroll
        for (int mf = 0; mf < 2; ++mf) {
            #pragma unroll
            for (int nf = 0; nf < 8; ++nf) {
                const int col = cbase + nf * 8;
                const float bz0 = Bias[col], bz1 = Bias[col + 1];
                const int r0 = rbase + mf * 16;
                float2 v0, v1;
                v0.x = fmaxf(acc[mf][nf][0] + bz0, 0.0f);
                v0.y = fmaxf(acc[mf][nf][1] + bz1, 0.0f);
                v1.x = fmaxf(acc[mf][nf][2] + bz0, 0.0f);
                v1.y = fmaxf(acc[mf][nf][3] + bz1, 0.0f);
                *reinterpret_cast<float2*>(out + (size_t)r0 * OUTD + col)       = v0;
                *reinterpret_cast<float2*>(out + (size_t)(r0 + 8) * OUTD + col) = v1;
            }
        }
    }
    #undef GEN_A
    #undef LOAD_B
}

// ---------------- launch ----------------
extern "C" void kernel_launch(void* const* d_in, const int* in_sizes, int n_in,
                              void* d_out, int out_size) {
    const float* x = (const float*)d_in[0];
    const float* W = (const float*)d_in[1];
    const float* b = (const float*)d_in[2];
    float* out = (float*)d_out;

    cudaFuncSetAttribute(taylor_main, cudaFuncAttributeMaxDynamicSharedMemorySize, SMEM_REQ);

    prep_all<<<(OUTD * KPAD + 255) / 256, 256>>>(W);
    taylor_main<<<BATCH / BM, NTHR, SMEM_REQ>>>(x, b, out);
}

// round 9
// speedup vs baseline: 1.4065x; 1.1143x over previous
#include <cuda_runtime.h>
#include <cuda_fp16.h>
#include <cstdint>

// ---------------- problem constants ----------------
#define BATCH  16384
#define NFEAT  16
#define MTOT   4844
#define KPAD   4864          // pad monomial = 1, pad W = 0
#define KSTAGE 64
#define NSTAGE 76
#define OUTD   256
#define BM     64            // batch rows per CTA -> grid 256, 2 CTAs/SM
#define NTHR   256           // 8 warps: 2 (M32) x 4 (N64)
#define EHSTR  162           // fp16 E row stride in halves (81 words, odd -> conflict-free)

// SMEM layout (bytes): XOR-swizzled 128B rows
#define A_BUFSZ 8192                           // 64 x 128B
#define B_BUFSZ 32768                          // 256 x 128B
#define A_OFF   0                              // 2 buffers -> 16384
#define B_OFF   (2 * A_BUFSZ)                  // 16384, 2 buffers -> +65536
#define E_OFF   (B_OFF + 2 * B_BUFSZ)          // 81920, Eh: 64*162*2 = 20736
#define SMEM_REQ (E_OFF + BM * EHSTR * 2)      // 102656 (2 CTAs = 205312 < SM cap)

// ---------------- device globals ----------------
__device__ __align__(16) __half   g_Wh[OUTD * KPAD];  // fp16 W [N=256][KPAD]
__device__ __align__(16) uint32_t g_TBL[KPAD];        // m -> e1 | (e2<<16)
__device__ uint32_t g_PAIRT[136];

__device__ __forceinline__ int pair_rank(int a, int b) {
    return a * 16 - (a * (a - 1)) / 2 + (b - a);
}

__global__ void prep_all(const float* __restrict__ W) {
    int idx = blockIdx.x * blockDim.x + threadIdx.x;
    if (idx < 136) {
        int r = idx, a = 0;
        while (r >= 16 - a) { r -= 16 - a; a++; }
        g_PAIRT[idx] = (uint32_t)a | ((uint32_t)(a + r) << 8);
    }
    if (idx < KPAD) {
        int m = idx;
        uint32_t e1 = 0, e2 = 0;
        if (m < 16) {
            e1 = 1 + m; e2 = 0;
        } else if (m < 152) {
            e1 = 17 + (m - 16); e2 = 0;
        } else if (m < 968) {
            int r = m - 152, a = 0;
            while (true) { int k = 16 - a; int t2 = k * (k + 1) / 2; if (r < t2) break; r -= t2; a++; }
            int b = a;
            while (r >= 16 - b) { r -= 16 - b; b++; }
            int c = b + r;
            e1 = 1 + a; e2 = 17 + pair_rank(b, c);
        } else if (m < MTOT) {
            int r = m - 968, a = 0;
            while (true) { int k = 16 - a; int t3 = k * (k + 1) * (k + 2) / 6; if (r < t3) break; r -= t3; a++; }
            int b = a;
            while (true) { int k = 16 - b; int t2 = k * (k + 1) / 2; if (r < t2) break; r -= t2; b++; }
            int c = b;
            while (r >= 16 - c) { r -= 16 - c; c++; }
            int d = c + r;
            e1 = 17 + pair_rank(a, b); e2 = 17 + pair_rank(c, d);
        } else {
            e1 = 0; e2 = 0;
        }
        g_TBL[m] = e1 | (e2 << 16);
    }
    if (idx < OUTD * KPAD) {
        int n = idx / KPAD, k = idx - n * KPAD;
        float w = (k < MTOT) ? W[(size_t)n * MTOT + k] : 0.0f;
        g_Wh[idx] = __float2half_rn(w);
    }
}

// ---------------- PTX helpers ----------------
__device__ __forceinline__ uint32_t smem_u32(const void* p) {
    uint32_t a;
    asm("{ .reg .u64 t; cvta.to.shared.u64 t, %1; cvt.u32.u64 %0, t; }" : "=r"(a) : "l"(p));
    return a;
}
__device__ __forceinline__ void cp_async16(uint32_t dst, const void* src) {
    asm volatile("cp.async.cg.shared.global [%0], [%1], 16;" :: "r"(dst), "l"(src) : "memory");
}
__device__ __forceinline__ void ldsm_x4(uint32_t (&r)[4], uint32_t addr) {
    asm volatile("ldmatrix.sync.aligned.m8n8.x4.shared.b16 {%0,%1,%2,%3}, [%4];"
                 : "=r"(r[0]), "=r"(r[1]), "=r"(r[2]), "=r"(r[3]) : "r"(addr));
}
__device__ __forceinline__ void mma16816(float (&c)[4], const uint32_t (&a)[4],
                                         uint32_t b0, uint32_t b1) {
    asm volatile(
        "mma.sync.aligned.m16n8k16.row.col.f32.f16.f16.f32 "
        "{%0,%1,%2,%3}, {%4,%5,%6,%7}, {%8,%9}, {%0,%1,%2,%3};"
        : "+f"(c[0]), "+f"(c[1]), "+f"(c[2]), "+f"(c[3])
        : "r"(a[0]), "r"(a[1]), "r"(a[2]), "r"(a[3]), "r"(b0), "r"(b1));
}

// ---------------- main fused kernel ----------------
// 256 CTAs x 256 threads (2 CTAs/SM). CTA tile M=64 x N=256, K staged by 64.
// 8 warps (wm 0..1, wn 0..3), warp tile M32 x N64. fp16 E-table.
__global__ void __launch_bounds__(NTHR, 2) taylor_main(
    const float* __restrict__ x,
    const float* __restrict__ bias,
    float* __restrict__ out)
{
    extern __shared__ char smem[];
    const uint32_t sbase = smem_u32(smem);
    __half* Eh = (__half*)(smem + E_OFF);

    const int tid  = threadIdx.x;
    const int wid  = tid >> 5;
    const int lane = tid & 31;
    const int b0   = blockIdx.x * BM;
    const int wm   = wid & 1;    // M block (32 rows)
    const int wn   = wid >> 1;   // N block (64 cols)

    // ---- prologue: tanh (fp32 scratch in A region) + pairwise products -> fp16 E ----
    {
        float* Tf = (float*)(smem + A_OFF);   // [64][17] fp32, dead after prologue
        #pragma unroll
        for (int i = 0; i < (BM * NFEAT) / NTHR; ++i) {
            int q = tid + i * NTHR;
            int row = q >> 4, f = q & 15;
            float t = tanhf(x[(size_t)(b0 + row) * NFEAT + f]);
            Tf[row * 17 + f] = t;
            Eh[row * EHSTR + 1 + f] = __float2half_rn(t);
        }
        if (tid < BM) Eh[tid * EHSTR] = __float2half_rn(1.0f);
        __syncthreads();
        #pragma unroll
        for (int i = 0; i < (136 * BM) / NTHR; ++i) {   // 34 iters, exact
            int q = tid + i * NTHR;
            int row = q & 63, p = q >> 6;
            uint32_t pr = g_PAIRT[p];
            Eh[row * EHSTR + 17 + p] = __float2half_rn(
                Tf[row * 17 + (pr & 255)] * Tf[row * 17 + ((pr >> 8) & 255)]);
        }
        __syncthreads();
    }

    // ---- gen assignment: row = tid&63, 16 k per thread at gkb ----
    const int grow = tid & 63;
    const int gkb  = (tid >> 6) << 4;      // 0,16,32,48
    const int gseg = gkb >> 3;             // 0,2,4,6
    const int grb  = grow & 7;
    const __half* Er = Eh + grow * EHSTR;
    const uint32_t gA0 = sbase + A_OFF + grow * 128 + (uint32_t)((gseg    ) ^ grb) * 16;
    const uint32_t gA1 = sbase + A_OFF + grow * 128 + (uint32_t)((gseg + 1) ^ grb) * 16;

    #define GEN_A(s_, bo_) do {                                                     \
        const int mb = (s_) * KSTAGE + gkb;                                         \
        uint32_t tt[16];                                                            \
        *(uint4*)&tt[0]  = *(const uint4*)&g_TBL[mb];                               \
        *(uint4*)&tt[4]  = *(const uint4*)&g_TBL[mb + 4];                           \
        *(uint4*)&tt[8]  = *(const uint4*)&g_TBL[mb + 8];                           \
        *(uint4*)&tt[12] = *(const uint4*)&g_TBL[mb + 12];                          \
        uint32_t hh[8];                                                             \
        _Pragma("unroll")                                                           \
        for (int q = 0; q < 8; ++q) {                                               \
            uint32_t t0 = tt[2 * q], t1 = tt[2 * q + 1];                            \
            __half p0 = __hmul(Er[t0 & 0xffff], Er[t0 >> 16]);                      \
            __half p1 = __hmul(Er[t1 & 0xffff], Er[t1 >> 16]);                      \
            hh[q] = (uint32_t)__half_as_ushort(p0) |                                \
                    ((uint32_t)__half_as_ushort(p1) << 16);                         \
        }                                                                           \
        asm volatile("st.shared.v4.b32 [%0], {%1,%2,%3,%4};"                        \
                     :: "r"(gA0 + (bo_)), "r"(hh[0]), "r"(hh[1]), "r"(hh[2]), "r"(hh[3]) : "memory"); \
        asm volatile("st.shared.v4.b32 [%0], {%1,%2,%3,%4};"                        \
                     :: "r"(gA1 + (bo_)), "r"(hh[4]), "r"(hh[5]), "r"(hh[6]), "r"(hh[7]) : "memory"); \
    } while (0)

    // B stage: 256 rows x 8 segs = 2048 chunks = 8 per thread (EXACT at 256 thr)
    #define LOAD_B(s_, bo_) do {                                                    \
        _Pragma("unroll")                                                           \
        for (int i = 0; i < 8; ++i) {                                               \
            int c = tid + i * NTHR;                                                 \
            int row = c >> 3, seg = c & 7;                                          \
            const __half* src = g_Wh + (size_t)row * KPAD + (s_) * KSTAGE + seg * 8;\
            cp_async16(sbase + B_OFF + (bo_) + row * 128 +                          \
                       (uint32_t)(seg ^ (row & 7)) * 16, src);                      \
        }                                                                           \
        asm volatile("cp.async.commit_group;" ::: "memory");                        \
    } while (0)

    // ---- pipeline prologue ----
    GEN_A(0, 0);
    LOAD_B(0, 0);
    GEN_A(1, A_BUFSZ);
    LOAD_B(1, B_BUFSZ);

    float acc[2][8][4];
    #pragma unroll
    for (int i = 0; i < 2; ++i)
        #pragma unroll
        for (int j = 0; j < 8; ++j)
            #pragma unroll
            for (int q = 0; q < 4; ++q) acc[i][j][q] = 0.0f;

    // ldsm lane addressing (logical seg -> phys via xor swizzle)
    const int ra   = wm * 32 + (lane & 15);
    const int arb  = ra & 7;
    const int alog = lane >> 4;
    const uint32_t aBase = sbase + A_OFF + ra * 128;

    const int bq    = lane >> 3;
    const int rbrow = wn * 64 + ((bq >> 1) << 3) + (lane & 7);
    const int brb   = rbrow & 7;
    const int blog  = bq & 1;
    const uint32_t bBase = sbase + B_OFF + rbrow * 128;

    // ---- main loop (2-deep, two barriers; sibling CTA hides the gaps) ----
    for (int s = 0; s < NSTAGE; ++s) {
        const int buf = s & 1;
        if (s == NSTAGE - 1)
            asm volatile("cp.async.wait_group 0;" ::: "memory");
        else
            asm volatile("cp.async.wait_group 1;" ::: "memory");
        __syncthreads();   // B(s) + A(s) visible

        const uint32_t aB = aBase + buf * A_BUFSZ;
        const uint32_t bB = bBase + buf * B_BUFSZ;
        #pragma unroll
        for (int kf = 0; kf < 4; ++kf) {
            uint32_t a[2][4];
            const uint32_t aoff = (uint32_t)((alog + 2 * kf) ^ arb) * 16;
            ldsm_x4(a[0], aB + aoff);
            ldsm_x4(a[1], aB + aoff + 16 * 128);
            const uint32_t boff = (uint32_t)((blog + 2 * kf) ^ brb) * 16;
            #pragma unroll
            for (int nb = 0; nb < 4; ++nb) {
                uint32_t b[4];
                ldsm_x4(b, bB + nb * (16 * 128) + boff);
                mma16816(acc[0][nb * 2 + 0], a[0], b[0], b[1]);
                mma16816(acc[0][nb * 2 + 1], a[0], b[2], b[3]);
                mma16816(acc[1][nb * 2 + 0], a[1], b[0], b[1]);
                mma16816(acc[1][nb * 2 + 1], a[1], b[2], b[3]);
            }
        }
        __syncthreads();   // all warps done reading buf

        if (s + 2 < NSTAGE) {
            LOAD_B(s + 2, buf * B_BUFSZ);   // cps in flight during gen
            GEN_A(s + 2, buf * A_BUFSZ);
        }
    }

    // ---- epilogue: bias + relu + store (bias via read-only cache) ----
    {
        const int rbase = b0 + wm * 32 + (lane >> 2);
        const int cbase = wn * 64 + (lane & 3) * 2;
        #pragma unroll
        for (int mf = 0; mf < 2; ++mf) {
            #pragma unroll
            for (int nf = 0; nf < 8; ++nf) {
                const int col = cbase + nf * 8;
                const float bz0 = __ldg(&bias[col]);
                const float bz1 = __ldg(&bias[col + 1]);
                const int r0 = rbase + mf * 16;
                float2 v0, v1;
                v0.x = fmaxf(acc[mf][nf][0] + bz0, 0.0f);
                v0.y = fmaxf(acc[mf][nf][1] + bz1, 0.0f);
                v1.x = fmaxf(acc[mf][nf][2] + bz0, 0.0f);
                v1.y = fmaxf(acc[mf][nf][3] + bz1, 0.0f);
                *reinterpret_cast<float2*>(out + (size_t)r0 * OUTD + col)       = v0;
                *reinterpret_cast<float2*>(out + (size_t)(r0 + 8) * OUTD + col) = v1;
            }
        }
    }
    #undef GEN_A
    #undef LOAD_B
}

// ---------------- launch ----------------
extern "C" void kernel_launch(void* const* d_in, const int* in_sizes, int n_in,
                              void* d_out, int out_size) {
    const float* x = (const float*)d_in[0];
    const float* W = (const float*)d_in[1];
    const float* b = (const float*)d_in[2];
    float* out = (float*)d_out;

    cudaFuncSetAttribute(taylor_main, cudaFuncAttributeMaxDynamicSharedMemorySize, SMEM_REQ);

    prep_all<<<(OUTD * KPAD + 255) / 256, 256>>>(W);
    taylor_main<<<BATCH / BM, NTHR, SMEM_REQ>>>(x, b, out);
}